// round 6
// baseline (speedup 1.0000x reference)
#include <cuda_runtime.h>
#include <math.h>

// KoLeoLoss — analytic reduction of the flat-stride-diagonal variant.
//
// Math recap (n=1024, d=256): the reference's flat[::n+1]=inf over the
// flattened (n,n,d) tensor excludes the self-pair ONLY at feature k=0,
// and for k=0 excludes exactly j=i. So m[i,k]=0 exactly for k>=1 and
// m[i,0] = min_{j!=i} |y_j - y_i| with y = L2-normalized column 0.
//
//   loss = -( sum_i log(NN_i + eps) + n*(d-1)*log(eps) ) / n
//
// Regime (established R1-R5): tiny workload => idle-DVFS clock; wall time is
// proportional to SERIAL CYCLES, not launches or bandwidth. So: 3 kernels
// chained with PDL (launch latency hidden), with the serial chain minimized:
// no atomics, no fences, no doubles, no long fmin/shfl chains.

#define KN   1024
#define KD   256
#define KEPS 1e-8f
#define NBLK 128
#define NTHR 256   // 8 warps

__device__ float g_y[KN];       // normalized column-0 values
__device__ float g_part[NBLK];  // per-block partial log-sums

// ---------------- K1: row norms -> g_y (warp-per-row) ----------------
__global__ void __launch_bounds__(NTHR, 1)
koleo_rownorm_kernel(const float* __restrict__ X) {
    const int t    = threadIdx.x;
    const int w    = t >> 5;
    const int lane = t & 31;
    const int row  = blockIdx.x * 8 + w;

    const float4* Xr = (const float4*)(X + row * KD);
    float4 a = Xr[lane];        // lane 0: a.x == X[row*KD + 0]
    float4 c = Xr[lane + 32];
    // Two independent FMA chains, joined once.
    float s0 = a.x*a.x + a.y*a.y + a.z*a.z + a.w*a.w;
    float s1 = c.x*c.x + c.y*c.y + c.z*c.z + c.w*c.w;
    float ss = s0 + s1;
    #pragma unroll
    for (int o = 16; o > 0; o >>= 1)
        ss += __shfl_xor_sync(0xFFFFFFFFu, ss, o);
    if (lane == 0) {
        // y = x0 / max(norm, eps); norm >= eps  <=>  ss >= eps^2.
        float y = (ss >= 1e-16f) ? a.x * rsqrtf(ss) : a.x * 1e8f;
        g_y[row] = y;
    }
    asm volatile("griddepcontrol.launch_dependents;");
}

// ---------------- K2: 1-D NN + per-block partial (warp-per-i) ----------------
__global__ void __launch_bounds__(NTHR, 1)
koleo_nn_kernel() {
    const int t    = threadIdx.x;
    const int w    = t >> 5;
    const int lane = t & 31;
    const int b    = blockIdx.x;
    const int i    = b * 8 + w;

    __shared__ float sy[KN];
    __shared__ float swsum[8];

    asm volatile("griddepcontrol.wait;" ::: "memory");

    // Stage all of g_y (4 KB): 256 threads x 1 float4.
    ((float4*)sy)[t] = ((const float4*)g_y)[t];
    __syncthreads();

    const float xi = sy[i];
    // Four independent min accumulators -> 4x shorter serial chain.
    float m0 = INFINITY, m1 = INFINITY, m2 = INFINITY, m3 = INFINITY;
    #pragma unroll
    for (int r = 0; r < 32; r += 4) {
        const int j0 = (r + 0) * 32 + lane;
        const int j1 = (r + 1) * 32 + lane;
        const int j2 = (r + 2) * 32 + lane;
        const int j3 = (r + 3) * 32 + lane;
        const float d0 = fabsf(sy[j0] - xi);
        const float d1 = fabsf(sy[j1] - xi);
        const float d2 = fabsf(sy[j2] - xi);
        const float d3 = fabsf(sy[j3] - xi);
        if (j0 != i) m0 = fminf(m0, d0);
        if (j1 != i) m1 = fminf(m1, d1);
        if (j2 != i) m2 = fminf(m2, d2);
        if (j3 != i) m3 = fminf(m3, d3);
    }
    float m = fminf(fminf(m0, m1), fminf(m2, m3));
    // Warp min in ONE instruction: float bits are order-preserving for
    // nonnegative values, so unsigned-min == float-min here.
    unsigned mb = __reduce_min_sync(0xFFFFFFFFu, __float_as_uint(m));
    if (lane == 0)
        swsum[w] = logf(__uint_as_float(mb) + KEPS);
    __syncthreads();

    if (t == 0) {
        // Fixed-order float sum: deterministic.
        float blk = 0.0f;
        #pragma unroll
        for (int k = 0; k < 8; k++) blk += swsum[k];
        g_part[b] = blk;
    }
    asm volatile("griddepcontrol.launch_dependents;");
}

// ---------------- K3: final 128-value sum (1 warp) ----------------
__global__ void __launch_bounds__(32, 1)
koleo_final_kernel(float* __restrict__ out) {
    const int lane = threadIdx.x;
    asm volatile("griddepcontrol.wait;" ::: "memory");

    float4 p = ((const float4*)g_part)[lane];   // 32 lanes x 4 = 128
    float s = (p.x + p.y) + (p.z + p.w);
    #pragma unroll
    for (int o = 16; o > 0; o >>= 1)
        s += __shfl_xor_sync(0xFFFFFFFFu, s, o);
    if (lane == 0) {
        const float cterm = (float)(KN * (KD - 1)) * logf(KEPS);
        out[0] = -(s + cterm) / (float)KN;
    }
}

extern "C" void kernel_launch(void* const* d_in, const int* in_sizes, int n_in,
                              void* d_out, int out_size) {
    (void)in_sizes; (void)n_in; (void)out_size;
    const float* X = (const float*)d_in[0];
    float* out = (float*)d_out;

    cudaLaunchAttribute attr[1];
    attr[0].id = cudaLaunchAttributeProgrammaticStreamSerialization;
    attr[0].val.programmaticStreamSerializationAllowed = 1;

    koleo_rownorm_kernel<<<NBLK, NTHR>>>(X);

    cudaLaunchConfig_t cfg2 = {};
    cfg2.gridDim = dim3(NBLK, 1, 1);
    cfg2.blockDim = dim3(NTHR, 1, 1);
    cfg2.stream = 0;
    cfg2.attrs = attr;
    cfg2.numAttrs = 1;
    cudaLaunchKernelEx(&cfg2, koleo_nn_kernel);

    cudaLaunchConfig_t cfg3 = {};
    cfg3.gridDim = dim3(1, 1, 1);
    cfg3.blockDim = dim3(32, 1, 1);
    cfg3.stream = 0;
    cfg3.attrs = attr;
    cfg3.numAttrs = 1;
    cudaLaunchKernelEx(&cfg3, koleo_final_kernel, out);
}